// round 4
// baseline (speedup 1.0000x reference)
#include <cuda_runtime.h>
#include <math_constants.h>

#define BATCH  4
#define SEQ    2048
#define DIM    1024
#define HEADS  16
#define GROUPS 4
#define DHEAD  64
#define KVD    512
#define M_ROWS (BATCH*SEQ)      /* 8192 */
#define QKV_N  (DIM + KVD)      /* 1536 */

// Scratch (allocation-free rule: __device__ globals)
__device__ float g_xn [M_ROWS * DIM];     // 32 MB: layernormed x
__device__ float g_qkv[M_ROWS * QKV_N];   // 48 MB: [q(1024) | k(256) | v(256)]
__device__ float g_ao [M_ROWS * DIM];     // 32 MB: attention output (b,n,h*d)

// ---------------------------------------------------------------------------
// Kernel 1: row LayerNorm over DIM=1024
// ---------------------------------------------------------------------------
__global__ void __launch_bounds__(256) ln_rows(const float* __restrict__ x,
                                               const float* __restrict__ sc,
                                               const float* __restrict__ bi) {
    int row = blockIdx.x;
    const float* xr = x + (size_t)row * DIM;
    float v[4];
    float s = 0.f, s2 = 0.f;
#pragma unroll
    for (int i = 0; i < 4; i++) {
        v[i] = xr[threadIdx.x + i * 256];
        s += v[i]; s2 += v[i] * v[i];
    }
    __shared__ float rs[8], rq[8];
#pragma unroll
    for (int o = 16; o; o >>= 1) {
        s  += __shfl_xor_sync(0xffffffffu, s,  o);
        s2 += __shfl_xor_sync(0xffffffffu, s2, o);
    }
    int warp = threadIdx.x >> 5, lane = threadIdx.x & 31;
    if (!lane) { rs[warp] = s; rq[warp] = s2; }
    __syncthreads();
    if (threadIdx.x == 0) {
        float a = 0.f, b = 0.f;
#pragma unroll
        for (int w = 0; w < 8; w++) { a += rs[w]; b += rq[w]; }
        rs[0] = a; rq[0] = b;
    }
    __syncthreads();
    float mu = rs[0] * (1.f / DIM);
    float r  = rsqrtf(rq[0] * (1.f / DIM) - mu * mu + 1e-6f);
    float* o = g_xn + (size_t)row * DIM;
#pragma unroll
    for (int i = 0; i < 4; i++) {
        int c = threadIdx.x + i * 256;
        o[c] = (v[i] - mu) * r * sc[c] + bi[c];
    }
}

// ---------------------------------------------------------------------------
// Shared 128x128x16 fp32 SGEMM body (256 threads, 8x8 register tile)
// ---------------------------------------------------------------------------
__device__ __forceinline__ void sgemm128(const float* __restrict__ A, int lda,
                                         const float* __restrict__ Bp, int ldb,
                                         float* __restrict__ C, int ldc,
                                         int rowbase, int colb, int colc, int K) {
    __shared__ float As[16][136];   // [k][m], padded
    __shared__ float Bs[16][128];   // [k][n]
    int tid = threadIdx.x;
    float acc[8][8];
#pragma unroll
    for (int i = 0; i < 8; i++)
#pragma unroll
        for (int j = 0; j < 8; j++) acc[i][j] = 0.f;
    int m0 = (tid >> 4) * 8, n0 = (tid & 15) * 8;

    for (int k0 = 0; k0 < K; k0 += 16) {
#pragma unroll
        for (int t = 0; t < 2; t++) {
            int idx = tid * 2 + t;                 // 0..511
            int r = idx >> 2, kq = (idx & 3) * 4;
            float4 f = *(const float4*)(A + (size_t)(rowbase + r) * lda + k0 + kq);
            As[kq + 0][r] = f.x; As[kq + 1][r] = f.y;
            As[kq + 2][r] = f.z; As[kq + 3][r] = f.w;
        }
#pragma unroll
        for (int t = 0; t < 2; t++) {
            int idx = tid * 2 + t;
            int kr = idx >> 5, n4 = (idx & 31) * 4;
            *(float4*)&Bs[kr][n4] =
                *(const float4*)(Bp + (size_t)(k0 + kr) * ldb + colb + n4);
        }
        __syncthreads();
#pragma unroll
        for (int k = 0; k < 16; k++) {
            float ar[8], br[8];
            *(float4*)&ar[0] = *(float4*)&As[k][m0];
            *(float4*)&ar[4] = *(float4*)&As[k][m0 + 4];
            *(float4*)&br[0] = *(float4*)&Bs[k][n0];
            *(float4*)&br[4] = *(float4*)&Bs[k][n0 + 4];
#pragma unroll
            for (int i = 0; i < 8; i++)
#pragma unroll
                for (int j = 0; j < 8; j++)
                    acc[i][j] += ar[i] * br[j];
        }
        __syncthreads();
    }
#pragma unroll
    for (int i = 0; i < 8; i++) {
        float* cr = C + (size_t)(rowbase + m0 + i) * ldc + colc + n0;
        *(float4*)&cr[0] = make_float4(acc[i][0], acc[i][1], acc[i][2], acc[i][3]);
        *(float4*)&cr[4] = make_float4(acc[i][4], acc[i][5], acc[i][6], acc[i][7]);
    }
}

// Kernel 2: qkv = xn @ [Wq | Wkv]   (N = 1536)
__global__ void __launch_bounds__(256) gemm_qkv(const float* __restrict__ Wq,
                                                const float* __restrict__ Wkv) {
    int nb = blockIdx.x;           // 0..11 (0..7 -> Wq, 8..11 -> Wkv)
    int rb = blockIdx.y * 128;
    const float* Bp; int ldb, colb;
    if (nb < 8) { Bp = Wq;  ldb = DIM; colb = nb * 128; }
    else        { Bp = Wkv; ldb = KVD; colb = (nb - 8) * 128; }
    sgemm128(g_xn, DIM, Bp, ldb, g_qkv, QKV_N, rb, colb, nb * 128, DIM);
}

// Kernel 5: out = attn_out @ Wout
__global__ void __launch_bounds__(256) gemm_out(const float* __restrict__ Wout,
                                                float* __restrict__ out) {
    sgemm128(g_ao, DIM, Wout, DIM, out, DIM,
             blockIdx.y * 128, blockIdx.x * 128, blockIdx.x * 128, DIM);
}

// ---------------------------------------------------------------------------
// Kernel 3: per-head LN on q (16 heads) and k (4 groups), in place on g_qkv.
// Attention scale 1/sqrt(64)=0.125 folded into q.
// ---------------------------------------------------------------------------
__global__ void head_ln(const float* __restrict__ qs, const float* __restrict__ qb,
                        const float* __restrict__ ks, const float* __restrict__ kb) {
    int row = blockIdx.x, seg = blockIdx.y;      // seg 0..15 = q heads, 16..19 = k groups
    bool isq = seg < 16;
    int col0 = isq ? seg * DHEAD : DIM + (seg - 16) * DHEAD;
    const float* sc = isq ? qs : ks;
    const float* bb = isq ? qb : kb;
    float* p = g_qkv + (size_t)row * QKV_N + col0;
    int lane = threadIdx.x;
    float a = p[lane], c = p[lane + 32];
    float s = a + c, s2 = a * a + c * c;
#pragma unroll
    for (int o = 16; o; o >>= 1) {
        s  += __shfl_xor_sync(0xffffffffu, s,  o);
        s2 += __shfl_xor_sync(0xffffffffu, s2, o);
    }
    float mu = s * (1.f / 64.f);
    float r  = rsqrtf(s2 * (1.f / 64.f) - mu * mu + 1e-6f);
    float mult = isq ? 0.125f : 1.0f;
    p[lane]      = ((a - mu) * r * sc[lane]      + bb[lane])      * mult;
    p[lane + 32] = ((c - mu) * r * sc[lane + 32] + bb[lane + 32]) * mult;
}

// ---------------------------------------------------------------------------
// Kernel 4: flash attention, fp32. Block = one (qtile of 64, b, h).
// Online softmax over key tiles of 64. d = 64.
// ---------------------------------------------------------------------------
#define QS_STRIDE 68   // padded, float4-aligned, kills stride-64 bank conflicts
#define PS_STRIDE 65
#define ATTN_SMEM ((64*QS_STRIDE*2 + 64*64 + 64*PS_STRIDE) * 4)   /* 67840 B */

__global__ void __launch_bounds__(256) attn_kernel() {
    extern __shared__ float sm[];
    float* Qs = sm;                      // 64 rows, stride 68
    float* Ks = Qs + 64 * QS_STRIDE;     // stride 68
    float* Vs = Ks + 64 * QS_STRIDE;     // stride 64 (aligned float4 reads)
    float* Ps = Vs + 64 * 64;            // stride 65 (scalar, conflict-free rows)

    int tid = threadIdx.x;
    int qt = blockIdx.x;
    int bh = blockIdx.y;
    int b = bh >> 4, h = bh & 15, g = h >> 2;

    const float* qb = g_qkv + (size_t)(b * SEQ + qt * 64) * QKV_N + h * DHEAD;
#pragma unroll
    for (int i = 0; i < 4; i++) {
        int idx = tid + i * 256;              // 0..1023
        int r = idx >> 4, c4 = (idx & 15) * 4;
        *(float4*)&Qs[r * QS_STRIDE + c4] =
            *(const float4*)(qb + (size_t)r * QKV_N + c4);
    }
    __syncthreads();

    float m_i = -CUDART_INF_F, l_i = 0.f;
    float O[16];
#pragma unroll
    for (int j = 0; j < 16; j++) O[j] = 0.f;

    int r0 = (tid >> 4) * 4, c0 = (tid & 15) * 4;     // S-phase mapping
    int row = tid >> 2, quad = tid & 3, dc0 = quad * 16;  // softmax/PV mapping

    const float* kb0 = g_qkv + (size_t)(b * SEQ) * QKV_N + DIM + g * DHEAD;
    const float* vb0 = kb0 + GROUPS * DHEAD;   // +256

    for (int kt = 0; kt < SEQ / 64; kt++) {
        const float* kb = kb0 + (size_t)kt * 64 * QKV_N;
        const float* vb = vb0 + (size_t)kt * 64 * QKV_N;
#pragma unroll
        for (int i = 0; i < 4; i++) {
            int idx = tid + i * 256;
            int r = idx >> 4, c4 = (idx & 15) * 4;
            *(float4*)&Ks[r * QS_STRIDE + c4] = *(const float4*)(kb + (size_t)r * QKV_N + c4);
            *(float4*)&Vs[r * 64        + c4] = *(const float4*)(vb + (size_t)r * QKV_N + c4);
        }
        __syncthreads();

        // --- S = Q K^T (q pre-scaled by 0.125) ---
        float acc[4][4];
#pragma unroll
        for (int i = 0; i < 4; i++)
#pragma unroll
            for (int j = 0; j < 4; j++) acc[i][j] = 0.f;
#pragma unroll
        for (int d4 = 0; d4 < 16; d4++) {
            float4 a[4], kk[4];
#pragma unroll
            for (int i = 0; i < 4; i++) a[i]  = *(float4*)&Qs[(r0 + i) * QS_STRIDE + d4 * 4];
#pragma unroll
            for (int j = 0; j < 4; j++) kk[j] = *(float4*)&Ks[(c0 + j) * QS_STRIDE + d4 * 4];
#pragma unroll
            for (int i = 0; i < 4; i++)
#pragma unroll
                for (int j = 0; j < 4; j++)
                    acc[i][j] += a[i].x * kk[j].x + a[i].y * kk[j].y
                               + a[i].z * kk[j].z + a[i].w * kk[j].w;
        }
#pragma unroll
        for (int i = 0; i < 4; i++)
#pragma unroll
            for (int j = 0; j < 4; j++)
                Ps[(r0 + i) * PS_STRIDE + c0 + j] = acc[i][j];
        __syncthreads();

        // --- online softmax: 4 lanes per row ---
        float* prow = Ps + row * PS_STRIDE;
        float tmax = -CUDART_INF_F;
#pragma unroll
        for (int c = quad; c < 64; c += 4) tmax = fmaxf(tmax, prow[c]);
        tmax = fmaxf(tmax, __shfl_xor_sync(0xffffffffu, tmax, 1));
        tmax = fmaxf(tmax, __shfl_xor_sync(0xffffffffu, tmax, 2));
        float mnew  = fmaxf(m_i, tmax);
        float alpha = __expf(m_i - mnew);
        float ls = 0.f;
#pragma unroll
        for (int c = quad; c < 64; c += 4) {
            float p = __expf(prow[c] - mnew);
            prow[c] = p;
            ls += p;
        }
        ls += __shfl_xor_sync(0xffffffffu, ls, 1);
        ls += __shfl_xor_sync(0xffffffffu, ls, 2);
        l_i = l_i * alpha + ls;
        m_i = mnew;
#pragma unroll
        for (int j = 0; j < 16; j++) O[j] *= alpha;
        __syncwarp();

        // --- O += P @ V (each thread: 1 row x 16 d-cols) ---
#pragma unroll 8
        for (int c = 0; c < 64; c++) {
            float p = prow[c];
            const float* vr = &Vs[c * 64 + dc0];
            float4 v0 = *(const float4*)(vr);
            float4 v1 = *(const float4*)(vr + 4);
            float4 v2 = *(const float4*)(vr + 8);
            float4 v3 = *(const float4*)(vr + 12);
            O[0]  += p * v0.x; O[1]  += p * v0.y; O[2]  += p * v0.z; O[3]  += p * v0.w;
            O[4]  += p * v1.x; O[5]  += p * v1.y; O[6]  += p * v1.z; O[7]  += p * v1.w;
            O[8]  += p * v2.x; O[9]  += p * v2.y; O[10] += p * v2.z; O[11] += p * v2.w;
            O[12] += p * v3.x; O[13] += p * v3.y; O[14] += p * v3.z; O[15] += p * v3.w;
        }
        __syncthreads();
    }

    float inv = 1.f / l_i;
    float* orow = g_ao + (size_t)(b * SEQ + qt * 64 + row) * DIM + h * DHEAD + dc0;
#pragma unroll
    for (int u = 0; u < 4; u++) {
        *(float4*)&orow[u * 4] = make_float4(O[u * 4 + 0] * inv, O[u * 4 + 1] * inv,
                                             O[u * 4 + 2] * inv, O[u * 4 + 3] * inv);
    }
}

// ---------------------------------------------------------------------------
extern "C" void kernel_launch(void* const* d_in, const int* in_sizes, int n_in,
                              void* d_out, int out_size) {
    (void)in_sizes; (void)n_in; (void)out_size;
    const float* x    = (const float*)d_in[0];
    const float* ln_s = (const float*)d_in[1];
    const float* ln_b = (const float*)d_in[2];
    const float* Wq   = (const float*)d_in[3];
    const float* Wkv  = (const float*)d_in[4];
    const float* qn_s = (const float*)d_in[5];
    const float* qn_b = (const float*)d_in[6];
    const float* kn_s = (const float*)d_in[7];
    const float* kn_b = (const float*)d_in[8];
    const float* Wout = (const float*)d_in[9];
    float* out = (float*)d_out;

    cudaFuncSetAttribute(attn_kernel,
                         cudaFuncAttributeMaxDynamicSharedMemorySize, ATTN_SMEM);

    ln_rows<<<M_ROWS, 256>>>(x, ln_s, ln_b);
    gemm_qkv<<<dim3(12, M_ROWS / 128), 256>>>(Wq, Wkv);
    head_ln<<<dim3(M_ROWS, 20), 32>>>(qn_s, qn_b, kn_s, kn_b);
    attn_kernel<<<dim3(SEQ / 64, BATCH * HEADS), 256, ATTN_SMEM>>>();
    gemm_out<<<dim3(DIM / 128, M_ROWS / 128), 256>>>(Wout, out);
}

// round 8
// speedup vs baseline: 5.3629x; 5.3629x over previous
#include <cuda_runtime.h>
#include <math_constants.h>
#include <cstdint>

#define BATCH  4
#define SEQ    2048
#define DIM    1024
#define HEADS  16
#define GROUPS 4
#define DHEAD  64
#define KVD    512
#define M_ROWS (BATCH*SEQ)      /* 8192 */
#define QKV_N  (DIM + KVD)      /* 1536 */

// Scratch (allocation-free rule: __device__ globals)
__device__ float g_xn [M_ROWS * DIM];     // layernormed x
__device__ float g_qkv[M_ROWS * QKV_N];   // [q(1024) | k(256) | v(256)]
__device__ float g_ao [M_ROWS * DIM];     // attention output (b,n,h*d)

// ---------------------------------------------------------------------------
// helpers: tf32 rounding + m16n8k8 tf32 mma
// ---------------------------------------------------------------------------
__device__ __forceinline__ float tf32r(float x) {
    uint32_t u;
    asm("cvt.rna.tf32.f32 %0, %1;" : "=r"(u) : "f"(x));
    return __uint_as_float(u);
}
__device__ __forceinline__ float4 tf32r4(float4 f) {
    f.x = tf32r(f.x); f.y = tf32r(f.y); f.z = tf32r(f.z); f.w = tf32r(f.w);
    return f;
}
__device__ __forceinline__ void mma8(float* c, const uint32_t* a, const uint32_t* b) {
    asm volatile(
        "mma.sync.aligned.m16n8k8.row.col.f32.tf32.tf32.f32 "
        "{%0,%1,%2,%3}, {%4,%5,%6,%7}, {%8,%9}, {%0,%1,%2,%3};\n"
        : "+f"(c[0]), "+f"(c[1]), "+f"(c[2]), "+f"(c[3])
        : "r"(a[0]), "r"(a[1]), "r"(a[2]), "r"(a[3]), "r"(b[0]), "r"(b[1]));
}
__device__ __forceinline__ uint32_t fbits(float x) { return __float_as_uint(x); }

// ---------------------------------------------------------------------------
// Kernel 1: row LayerNorm over DIM=1024
// ---------------------------------------------------------------------------
__global__ void __launch_bounds__(256) ln_rows(const float* __restrict__ x,
                                               const float* __restrict__ sc,
                                               const float* __restrict__ bi) {
    int row = blockIdx.x;
    const float* xr = x + (size_t)row * DIM;
    float v[4];
    float s = 0.f, s2 = 0.f;
#pragma unroll
    for (int i = 0; i < 4; i++) {
        v[i] = xr[threadIdx.x + i * 256];
        s += v[i]; s2 += v[i] * v[i];
    }
    __shared__ float rs[8], rq[8];
#pragma unroll
    for (int o = 16; o; o >>= 1) {
        s  += __shfl_xor_sync(0xffffffffu, s,  o);
        s2 += __shfl_xor_sync(0xffffffffu, s2, o);
    }
    int warp = threadIdx.x >> 5, lane = threadIdx.x & 31;
    if (!lane) { rs[warp] = s; rq[warp] = s2; }
    __syncthreads();
    if (threadIdx.x == 0) {
        float a = 0.f, b = 0.f;
#pragma unroll
        for (int w = 0; w < 8; w++) { a += rs[w]; b += rq[w]; }
        rs[0] = a; rq[0] = b;
    }
    __syncthreads();
    float mu = rs[0] * (1.f / DIM);
    float r  = rsqrtf(rq[0] * (1.f / DIM) - mu * mu + 1e-6f);
    float* o = g_xn + (size_t)row * DIM;
#pragma unroll
    for (int i = 0; i < 4; i++) {
        int c = threadIdx.x + i * 256;
        o[c] = (v[i] - mu) * r * sc[c] + bi[c];
    }
}

// ---------------------------------------------------------------------------
// tf32 tensor-core GEMM body: 128x128 block tile, 8 warps (4x2), warp 32x64
// smem k-major [k][136] — frag gathers bank-conflict-free
// ---------------------------------------------------------------------------
__device__ __forceinline__ void mmgemm(const float* __restrict__ A, int lda,
                                       const float* __restrict__ Bp, int ldb,
                                       float* __restrict__ C, int ldc,
                                       int rowbase, int colb, int colc, int K) {
    __shared__ float As[16][136];
    __shared__ float Bs[16][136];
    int tid = threadIdx.x, lane = tid & 31, w = tid >> 5;
    int l4 = lane >> 2, lm4 = lane & 3;
    int m0w = 32 * (w & 3), n0w = 64 * (w >> 2);

    float Cf[2][8][4];
#pragma unroll
    for (int mt = 0; mt < 2; mt++)
#pragma unroll
        for (int nt = 0; nt < 8; nt++)
#pragma unroll
            for (int i = 0; i < 4; i++) Cf[mt][nt][i] = 0.f;

    for (int k0 = 0; k0 < K; k0 += 16) {
#pragma unroll
        for (int t = 0; t < 2; t++) {
            int idx = tid * 2 + t;                 // 0..511
            int r = idx >> 2, kq = (idx & 3) * 4;
            float4 f = tf32r4(*(const float4*)(A + (size_t)(rowbase + r) * lda + k0 + kq));
            As[kq + 0][r] = f.x; As[kq + 1][r] = f.y;
            As[kq + 2][r] = f.z; As[kq + 3][r] = f.w;
        }
#pragma unroll
        for (int t = 0; t < 2; t++) {
            int idx = tid * 2 + t;
            int kr = idx >> 5, n4 = (idx & 31) * 4;
            *(float4*)&Bs[kr][n4] =
                tf32r4(*(const float4*)(Bp + (size_t)(k0 + kr) * ldb + colb + n4));
        }
        __syncthreads();
#pragma unroll
        for (int ks = 0; ks < 16; ks += 8) {
            uint32_t af[2][4];
#pragma unroll
            for (int mt = 0; mt < 2; mt++) {
                int m = m0w + 16 * mt;
                af[mt][0] = fbits(As[ks + lm4    ][m + l4    ]);
                af[mt][1] = fbits(As[ks + lm4    ][m + l4 + 8]);
                af[mt][2] = fbits(As[ks + lm4 + 4][m + l4    ]);
                af[mt][3] = fbits(As[ks + lm4 + 4][m + l4 + 8]);
            }
#pragma unroll
            for (int nt = 0; nt < 8; nt++) {
                uint32_t bf[2];
                bf[0] = fbits(Bs[ks + lm4    ][n0w + 8 * nt + l4]);
                bf[1] = fbits(Bs[ks + lm4 + 4][n0w + 8 * nt + l4]);
                mma8(Cf[0][nt], af[0], bf);
                mma8(Cf[1][nt], af[1], bf);
            }
        }
        __syncthreads();
    }
#pragma unroll
    for (int mt = 0; mt < 2; mt++)
#pragma unroll
        for (int nt = 0; nt < 8; nt++) {
            int r = rowbase + m0w + 16 * mt + l4;
            int c = colc + n0w + 8 * nt + 2 * lm4;
            *(float2*)&C[(size_t)r * ldc + c] =
                make_float2(Cf[mt][nt][0], Cf[mt][nt][1]);
            *(float2*)&C[(size_t)(r + 8) * ldc + c] =
                make_float2(Cf[mt][nt][2], Cf[mt][nt][3]);
        }
}

// Kernel 2: qkv = xn @ [Wq | Wkv]
__global__ void __launch_bounds__(256) gemm_qkv(const float* __restrict__ Wq,
                                                const float* __restrict__ Wkv) {
    int nb = blockIdx.x;
    int rb = blockIdx.y * 128;
    const float* Bp; int ldb, colb;
    if (nb < 8) { Bp = Wq;  ldb = DIM; colb = nb * 128; }
    else        { Bp = Wkv; ldb = KVD; colb = (nb - 8) * 128; }
    mmgemm(g_xn, DIM, Bp, ldb, g_qkv, QKV_N, rb, colb, nb * 128, DIM);
}

// Kernel 5: out = attn_out @ Wout
__global__ void __launch_bounds__(256) gemm_out(const float* __restrict__ Wout,
                                                float* __restrict__ out) {
    mmgemm(g_ao, DIM, Wout, DIM, out, DIM,
           blockIdx.y * 128, blockIdx.x * 128, blockIdx.x * 128, DIM);
}

// ---------------------------------------------------------------------------
// Kernel 3: per-head LN on q/k, attention scale folded into q
// ---------------------------------------------------------------------------
__global__ void head_ln(const float* __restrict__ qs, const float* __restrict__ qb,
                        const float* __restrict__ ks, const float* __restrict__ kb) {
    int row = blockIdx.x, seg = blockIdx.y;
    bool isq = seg < 16;
    int col0 = isq ? seg * DHEAD : DIM + (seg - 16) * DHEAD;
    const float* sc = isq ? qs : ks;
    const float* bb = isq ? qb : kb;
    float* p = g_qkv + (size_t)row * QKV_N + col0;
    int lane = threadIdx.x;
    float a = p[lane], c = p[lane + 32];
    float s = a + c, s2 = a * a + c * c;
#pragma unroll
    for (int o = 16; o; o >>= 1) {
        s  += __shfl_xor_sync(0xffffffffu, s,  o);
        s2 += __shfl_xor_sync(0xffffffffu, s2, o);
    }
    float mu = s * (1.f / 64.f);
    float r  = rsqrtf(s2 * (1.f / 64.f) - mu * mu + 1e-6f);
    float mult = isq ? 0.125f : 1.0f;
    p[lane]      = ((a - mu) * r * sc[lane]      + bb[lane])      * mult;
    p[lane + 32] = ((c - mu) * r * sc[lane + 32] + bb[lane + 32]) * mult;
}

// ---------------------------------------------------------------------------
// Kernel 4: flash attention with tf32 mma. Block = (64 q rows, b, h).
// 8 warps: warp (wr=w&3 -> 16 q rows, wc=w>>2 -> 32 cols of S / of d)
// smem stride 68 everywhere -> frag gathers bank-conflict-free.
// ---------------------------------------------------------------------------
#define AS 68
#define ATTN_SMEM ((4*64*AS + 128) * 4)   /* 70144 B */

__global__ void __launch_bounds__(256) attn_kernel() {
    extern __shared__ float sm[];
    float* Qs = sm;
    float* Ks = Qs + 64 * AS;
    float* Vs = Ks + 64 * AS;
    float* Ps = Vs + 64 * AS;
    float* Al = Ps + 64 * AS;   // 64 alphas
    float* Li = Al + 64;        // 64 1/l

    int tid = threadIdx.x, lane = tid & 31, w = tid >> 5;
    int l4 = lane >> 2, lm4 = lane & 3;
    int wr = w & 3, wc = w >> 2;
    int qt = blockIdx.x, bh = blockIdx.y;
    int b = bh >> 4, h = bh & 15, g = h >> 2;

    // ---- load Q tile (tf32-rounded) ----
    const float* qb = g_qkv + (size_t)(b * SEQ + qt * 64) * QKV_N + h * DHEAD;
#pragma unroll
    for (int i = 0; i < 4; i++) {
        int idx = tid + i * 256;
        int r = idx >> 4, c4 = (idx & 15) * 4;
        *(float4*)&Qs[r * AS + c4] = tf32r4(*(const float4*)(qb + (size_t)r * QKV_N + c4));
    }
    __syncthreads();

    // ---- hoist Q fragments into registers (reused for all 32 key tiles) ----
    uint32_t Qf[8][4];
    int qr = 16 * wr;
#pragma unroll
    for (int ks = 0; ks < 8; ks++) {
        Qf[ks][0] = fbits(Qs[(qr + l4    ) * AS + 8 * ks + lm4    ]);
        Qf[ks][1] = fbits(Qs[(qr + l4 + 8) * AS + 8 * ks + lm4    ]);
        Qf[ks][2] = fbits(Qs[(qr + l4    ) * AS + 8 * ks + lm4 + 4]);
        Qf[ks][3] = fbits(Qs[(qr + l4 + 8) * AS + 8 * ks + lm4 + 4]);
    }

    float Of[4][4];
#pragma unroll
    for (int nt = 0; nt < 4; nt++)
#pragma unroll
        for (int i = 0; i < 4; i++) Of[nt][i] = 0.f;
    float m_i = -CUDART_INF_F, l_i = 0.f;
    int srow = tid >> 2, quad = tid & 3;

    const float* kb0 = g_qkv + (size_t)(b * SEQ) * QKV_N + DIM + g * DHEAD;
    const float* vb0 = kb0 + GROUPS * DHEAD;

    for (int kt = 0; kt < SEQ / 64; kt++) {
        const float* kb = kb0 + (size_t)kt * 64 * QKV_N;
        const float* vb = vb0 + (size_t)kt * 64 * QKV_N;
#pragma unroll
        for (int i = 0; i < 4; i++) {
            int idx = tid + i * 256;
            int r = idx >> 4, c4 = (idx & 15) * 4;
            *(float4*)&Ks[r * AS + c4] = tf32r4(*(const float4*)(kb + (size_t)r * QKV_N + c4));
            *(float4*)&Vs[r * AS + c4] = tf32r4(*(const float4*)(vb + (size_t)r * QKV_N + c4));
        }
        __syncthreads();

        // ---- S = Q K^T (q pre-scaled by 0.125 in head_ln) ----
        float Sa[4][4];
#pragma unroll
        for (int nt = 0; nt < 4; nt++)
#pragma unroll
            for (int i = 0; i < 4; i++) Sa[nt][i] = 0.f;
#pragma unroll
        for (int ks = 0; ks < 8; ks++) {
#pragma unroll
            for (int nt = 0; nt < 4; nt++) {
                uint32_t bf[2];
                int key = 32 * wc + 8 * nt + l4;
                bf[0] = fbits(Ks[key * AS + 8 * ks + lm4    ]);
                bf[1] = fbits(Ks[key * AS + 8 * ks + lm4 + 4]);
                mma8(Sa[nt], Qf[ks], bf);
            }
        }
        // store S fragments to Ps
#pragma unroll
        for (int nt = 0; nt < 4; nt++) {
            int c0 = 32 * wc + 8 * nt + 2 * lm4;
            int r0 = 16 * wr + l4;
            *(float2*)&Ps[r0 * AS + c0]       = make_float2(Sa[nt][0], Sa[nt][1]);
            *(float2*)&Ps[(r0 + 8) * AS + c0] = make_float2(Sa[nt][2], Sa[nt][3]);
        }
        __syncthreads();

        // ---- online softmax: 4 lanes per row ----
        float* prow = Ps + srow * AS;
        float tmax = -CUDART_INF_F;
#pragma unroll
        for (int c = quad; c < 64; c += 4) tmax = fmaxf(tmax, prow[c]);
        tmax = fmaxf(tmax, __shfl_xor_sync(0xffffffffu, tmax, 1));
        tmax = fmaxf(tmax, __shfl_xor_sync(0xffffffffu, tmax, 2));
        float mnew  = fmaxf(m_i, tmax);
        float alpha = __expf(m_i - mnew);
        float ls = 0.f;
#pragma unroll
        for (int c = quad; c < 64; c += 4) {
            float p = tf32r(__expf(prow[c] - mnew));
            prow[c] = p;
            ls += p;
        }
        ls += __shfl_xor_sync(0xffffffffu, ls, 1);
        ls += __shfl_xor_sync(0xffffffffu, ls, 2);
        l_i = l_i * alpha + ls;
        m_i = mnew;
        if (quad == 0) Al[srow] = alpha;
        __syncthreads();

        // ---- O = O*alpha + P @ V ----
        float aLo = Al[16 * wr + l4], aHi = Al[16 * wr + l4 + 8];
#pragma unroll
        for (int nt = 0; nt < 4; nt++) {
            Of[nt][0] *= aLo; Of[nt][1] *= aLo;
            Of[nt][2] *= aHi; Of[nt][3] *= aHi;
        }
#pragma unroll
        for (int ks = 0; ks < 8; ks++) {
            uint32_t pa[4];
            pa[0] = fbits(Ps[(16 * wr + l4    ) * AS + 8 * ks + lm4    ]);
            pa[1] = fbits(Ps[(16 * wr + l4 + 8) * AS + 8 * ks + lm4    ]);
            pa[2] = fbits(Ps[(16 * wr + l4    ) * AS + 8 * ks + lm4 + 4]);
            pa[3] = fbits(Ps[(16 * wr + l4 + 8) * AS + 8 * ks + lm4 + 4]);
#pragma unroll
            for (int nt = 0; nt < 4; nt++) {
                uint32_t bf[2];
                int d0 = 32 * wc + 8 * nt + l4;
                bf[0] = fbits(Vs[(8 * ks + lm4    ) * AS + d0]);
                bf[1] = fbits(Vs[(8 * ks + lm4 + 4) * AS + d0]);
                mma8(Of[nt], pa, bf);
            }
        }
        __syncthreads();
    }

    if (quad == 0) Li[srow] = 1.f / l_i;
    __syncthreads();

    float liLo = Li[16 * wr + l4], liHi = Li[16 * wr + l4 + 8];
#pragma unroll
    for (int nt = 0; nt < 4; nt++) {
        int c0 = h * 64 + 32 * wc + 8 * nt + 2 * lm4;
        float* o0 = g_ao + (size_t)(b * SEQ + qt * 64 + 16 * wr + l4) * DIM + c0;
        *(float2*)o0 = make_float2(Of[nt][0] * liLo, Of[nt][1] * liLo);
        float* o1 = o0 + (size_t)8 * DIM;
        *(float2*)o1 = make_float2(Of[nt][2] * liHi, Of[nt][3] * liHi);
    }
}

// ---------------------------------------------------------------------------
extern "C" void kernel_launch(void* const* d_in, const int* in_sizes, int n_in,
                              void* d_out, int out_size) {
    (void)in_sizes; (void)n_in; (void)out_size;
    const float* x    = (const float*)d_in[0];
    const float* ln_s = (const float*)d_in[1];
    const float* ln_b = (const float*)d_in[2];
    const float* Wq   = (const float*)d_in[3];
    const float* Wkv  = (const float*)d_in[4];
    const float* qn_s = (const float*)d_in[5];
    const float* qn_b = (const float*)d_in[6];
    const float* kn_s = (const float*)d_in[7];
    const float* kn_b = (const float*)d_in[8];
    const float* Wout = (const float*)d_in[9];
    float* out = (float*)d_out;

    cudaFuncSetAttribute(attn_kernel,
                         cudaFuncAttributeMaxDynamicSharedMemorySize, ATTN_SMEM);

    ln_rows<<<M_ROWS, 256>>>(x, ln_s, ln_b);
    gemm_qkv<<<dim3(12, M_ROWS / 128), 256>>>(Wq, Wkv);
    head_ln<<<dim3(M_ROWS, 20), 32>>>(qn_s, qn_b, kn_s, kn_b);
    attn_kernel<<<dim3(SEQ / 64, BATCH * HEADS), 256, ATTN_SMEM>>>();
    gemm_out<<<dim3(DIM / 128, M_ROWS / 128), 256>>>(Wout, out);
}

// round 9
// speedup vs baseline: 7.6127x; 1.4195x over previous
#include <cuda_runtime.h>
#include <math_constants.h>
#include <cstdint>

#define BATCH  4
#define SEQ    2048
#define DIM    1024
#define HEADS  16
#define GROUPS 4
#define DHEAD  64
#define KVD    512
#define M_ROWS (BATCH*SEQ)      /* 8192 */
#define QKV_N  (DIM + KVD)      /* 1536 */

// Scratch (allocation-free rule: __device__ globals). All tf32-pre-rounded.
__device__ float g_xn  [M_ROWS * DIM];
__device__ float g_qkv [M_ROWS * QKV_N];
__device__ float g_ao  [M_ROWS * DIM];
__device__ float g_wq  [DIM * DIM];
__device__ float g_wkv [DIM * KVD];
__device__ float g_wout[DIM * DIM];

// ---------------------------------------------------------------------------
// helpers
// ---------------------------------------------------------------------------
__device__ __forceinline__ float tf32r(float x) {
    uint32_t u;
    asm("cvt.rna.tf32.f32 %0, %1;" : "=r"(u) : "f"(x));
    return __uint_as_float(u);
}
__device__ __forceinline__ float4 tf32r4(float4 f) {
    f.x = tf32r(f.x); f.y = tf32r(f.y); f.z = tf32r(f.z); f.w = tf32r(f.w);
    return f;
}
__device__ __forceinline__ void mma8(float* c, const uint32_t* a, const uint32_t* b) {
    asm volatile(
        "mma.sync.aligned.m16n8k8.row.col.f32.tf32.tf32.f32 "
        "{%0,%1,%2,%3}, {%4,%5,%6,%7}, {%8,%9}, {%0,%1,%2,%3};\n"
        : "+f"(c[0]), "+f"(c[1]), "+f"(c[2]), "+f"(c[3])
        : "r"(a[0]), "r"(a[1]), "r"(a[2]), "r"(a[3]), "r"(b[0]), "r"(b[1]));
}
__device__ __forceinline__ uint32_t fbits(float x) { return __float_as_uint(x); }

__device__ __forceinline__ void cpa16(uint32_t dst, const float* src) {
    asm volatile("cp.async.cg.shared.global [%0], [%1], 16;\n" :: "r"(dst), "l"(src));
}
#define CP_COMMIT() asm volatile("cp.async.commit_group;\n" ::: "memory")
template<int N> __device__ __forceinline__ void cp_wait() {
    asm volatile("cp.async.wait_group %0;\n" :: "n"(N) : "memory");
}

#define SCALE_LOG2E 0.18033688011112042f   /* 0.125 * log2(e) */

// ---------------------------------------------------------------------------
// Kernel 0: round weights into tf32 copies
// ---------------------------------------------------------------------------
__global__ void __launch_bounds__(256) round_weights(const float* __restrict__ Wq,
                                                     const float* __restrict__ Wkv,
                                                     const float* __restrict__ Wout) {
    int i = (blockIdx.x * 256 + threadIdx.x) * 4;
    const int NQ = DIM * DIM, NKV = DIM * KVD;
    if (i < NQ) {
        *(float4*)(g_wq + i) = tf32r4(*(const float4*)(Wq + i));
    } else if (i < NQ + NKV) {
        int j = i - NQ;
        *(float4*)(g_wkv + j) = tf32r4(*(const float4*)(Wkv + j));
    } else {
        int j = i - NQ - NKV;
        if (j < DIM * DIM)
            *(float4*)(g_wout + j) = tf32r4(*(const float4*)(Wout + j));
    }
}

// ---------------------------------------------------------------------------
// Kernel 1: row LayerNorm over DIM=1024, tf32-rounded output
// ---------------------------------------------------------------------------
__global__ void __launch_bounds__(256) ln_rows(const float* __restrict__ x,
                                               const float* __restrict__ sc,
                                               const float* __restrict__ bi) {
    int row = blockIdx.x;
    const float* xr = x + (size_t)row * DIM;
    float v[4];
    float s = 0.f, s2 = 0.f;
#pragma unroll
    for (int i = 0; i < 4; i++) {
        v[i] = xr[threadIdx.x + i * 256];
        s += v[i]; s2 += v[i] * v[i];
    }
    __shared__ float rs[8], rq[8];
#pragma unroll
    for (int o = 16; o; o >>= 1) {
        s  += __shfl_xor_sync(0xffffffffu, s,  o);
        s2 += __shfl_xor_sync(0xffffffffu, s2, o);
    }
    int warp = threadIdx.x >> 5, lane = threadIdx.x & 31;
    if (!lane) { rs[warp] = s; rq[warp] = s2; }
    __syncthreads();
    if (threadIdx.x == 0) {
        float a = 0.f, b = 0.f;
#pragma unroll
        for (int w = 0; w < 8; w++) { a += rs[w]; b += rq[w]; }
        rs[0] = a; rq[0] = b;
    }
    __syncthreads();
    float mu = rs[0] * (1.f / DIM);
    float r  = rsqrtf(rq[0] * (1.f / DIM) - mu * mu + 1e-6f);
    float* o = g_xn + (size_t)row * DIM;
#pragma unroll
    for (int i = 0; i < 4; i++) {
        int c = threadIdx.x + i * 256;
        o[c] = tf32r((v[i] - mu) * r * sc[c] + bi[c]);
    }
}

// ---------------------------------------------------------------------------
// tf32 GEMM: 128x128 tile, cp.async double-buffered, 8 warps (4x2)
// As row-major stride 20 (frag gathers conflict-free); Bs k-major stride 136
// ---------------------------------------------------------------------------
__device__ __forceinline__ void mmgemm(const float* __restrict__ A, int lda,
                                       const float* __restrict__ Bp, int ldb,
                                       float* __restrict__ C, int ldc,
                                       int rowbase, int colb, int colc) {
    __shared__ float As[2][128][20];
    __shared__ float Bs[2][16][136];
    int tid = threadIdx.x, lane = tid & 31, w = tid >> 5;
    int l4 = lane >> 2, lm4 = lane & 3;
    int m0w = 32 * (w & 3), n0w = 64 * (w >> 2);
    uint32_t aB = (uint32_t)__cvta_generic_to_shared(&As[0][0][0]);
    uint32_t bB = (uint32_t)__cvta_generic_to_shared(&Bs[0][0][0]);

    float Cf[2][8][4];
#pragma unroll
    for (int mt = 0; mt < 2; mt++)
#pragma unroll
        for (int nt = 0; nt < 8; nt++)
#pragma unroll
            for (int i = 0; i < 4; i++) Cf[mt][nt][i] = 0.f;

    const int NIT = DIM / 16;   // K = 1024 for both GEMMs

#define GFILL(k0, st)                                                          \
    {                                                                          \
        _Pragma("unroll")                                                      \
        for (int t = 0; t < 2; t++) {                                          \
            int idx = tid + t * 256;                                           \
            int ra = idx >> 2, ca = (idx & 3) * 4;                             \
            cpa16(aB + (uint32_t)((st) * 2560 + ra * 20 + ca) * 4,             \
                  A + (size_t)(rowbase + ra) * lda + (k0) + ca);               \
            int rb = idx >> 5, cb = (idx & 31) * 4;                            \
            cpa16(bB + (uint32_t)((st) * 2176 + rb * 136 + cb) * 4,            \
                  Bp + (size_t)((k0) + rb) * ldb + colb + cb);                 \
        }                                                                      \
        CP_COMMIT();                                                           \
    }

    GFILL(0, 0);
    for (int it = 0; it < NIT; it++) {
        int s = it & 1;
        if (it + 1 < NIT) { GFILL((it + 1) * 16, s ^ 1); cp_wait<1>(); }
        else              { cp_wait<0>(); }
        __syncthreads();
#pragma unroll
        for (int ks = 0; ks < 2; ks++) {
            uint32_t af[2][4];
#pragma unroll
            for (int mt = 0; mt < 2; mt++) {
                int m = m0w + 16 * mt;
                af[mt][0] = fbits(As[s][m + l4    ][8 * ks + lm4]);
                af[mt][1] = fbits(As[s][m + l4 + 8][8 * ks + lm4]);
                af[mt][2] = fbits(As[s][m + l4    ][8 * ks + lm4 + 4]);
                af[mt][3] = fbits(As[s][m + l4 + 8][8 * ks + lm4 + 4]);
            }
#pragma unroll
            for (int nt = 0; nt < 8; nt++) {
                uint32_t bf[2];
                bf[0] = fbits(Bs[s][8 * ks + lm4    ][n0w + 8 * nt + l4]);
                bf[1] = fbits(Bs[s][8 * ks + lm4 + 4][n0w + 8 * nt + l4]);
                mma8(Cf[0][nt], af[0], bf);
                mma8(Cf[1][nt], af[1], bf);
            }
        }
        __syncthreads();
    }
#undef GFILL
#pragma unroll
    for (int mt = 0; mt < 2; mt++)
#pragma unroll
        for (int nt = 0; nt < 8; nt++) {
            int r = rowbase + m0w + 16 * mt + l4;
            int c = colc + n0w + 8 * nt + 2 * lm4;
            *(float2*)&C[(size_t)r * ldc + c] =
                make_float2(Cf[mt][nt][0], Cf[mt][nt][1]);
            *(float2*)&C[(size_t)(r + 8) * ldc + c] =
                make_float2(Cf[mt][nt][2], Cf[mt][nt][3]);
        }
}

__global__ void __launch_bounds__(256) gemm_qkv() {
    int nb = blockIdx.x;
    int rb = blockIdx.y * 128;
    const float* Bp; int ldb, colb;
    if (nb < 8) { Bp = g_wq;  ldb = DIM; colb = nb * 128; }
    else        { Bp = g_wkv; ldb = KVD; colb = (nb - 8) * 128; }
    mmgemm(g_xn, DIM, Bp, ldb, g_qkv, QKV_N, rb, colb, nb * 128);
}

__global__ void __launch_bounds__(256) gemm_out(float* __restrict__ out) {
    mmgemm(g_ao, DIM, g_wout, DIM, out, DIM,
           blockIdx.y * 128, blockIdx.x * 128, blockIdx.x * 128);
}

// ---------------------------------------------------------------------------
// Kernel 3: per-head LN on q (x 0.125*log2e) and k; tf32 rounding on q,k,v
// seg 0..15 = q heads, 16..19 = k groups, 20..23 = v groups (round only)
// ---------------------------------------------------------------------------
__global__ void head_ln(const float* __restrict__ qs, const float* __restrict__ qb,
                        const float* __restrict__ ks, const float* __restrict__ kb) {
    int row = blockIdx.x, seg = blockIdx.y;
    int lane = threadIdx.x;
    if (seg >= 20) {
        float* p = g_qkv + (size_t)row * QKV_N + DIM + KVD / 2 + (seg - 20) * DHEAD;
        p[lane]      = tf32r(p[lane]);
        p[lane + 32] = tf32r(p[lane + 32]);
        return;
    }
    bool isq = seg < 16;
    int col0 = isq ? seg * DHEAD : DIM + (seg - 16) * DHEAD;
    const float* sc = isq ? qs : ks;
    const float* bb = isq ? qb : kb;
    float* p = g_qkv + (size_t)row * QKV_N + col0;
    float a = p[lane], c = p[lane + 32];
    float s = a + c, s2 = a * a + c * c;
#pragma unroll
    for (int o = 16; o; o >>= 1) {
        s  += __shfl_xor_sync(0xffffffffu, s,  o);
        s2 += __shfl_xor_sync(0xffffffffu, s2, o);
    }
    float mu = s * (1.f / 64.f);
    float r  = rsqrtf(s2 * (1.f / 64.f) - mu * mu + 1e-6f);
    float mult = isq ? SCALE_LOG2E : 1.0f;
    p[lane]      = tf32r(((a - mu) * r * sc[lane]      + bb[lane])      * mult);
    p[lane + 32] = tf32r(((c - mu) * r * sc[lane + 32] + bb[lane + 32]) * mult);
}

// ---------------------------------------------------------------------------
// Kernel 4: flash attention, tf32 mma, register-resident softmax.
// Block = 128 q rows x (b,h). 8 warps, each: 16 q rows x ALL 64 keys.
// K/V double-buffered via cp.async; S never touches smem.
// ---------------------------------------------------------------------------
#define AT_STAGE (2 * 64 * 68)              /* floats per stage (K + V) */
#define ATTN_SMEM (2 * AT_STAGE * 4)        /* 69632 bytes */

__global__ void __launch_bounds__(256) attn_kernel() {
    extern __shared__ float sm[];
    int tid = threadIdx.x, lane = tid & 31, w = tid >> 5;
    int l4 = lane >> 2, lm4 = lane & 3;
    int qt = blockIdx.x, bh = blockIdx.y;
    int b = bh >> 4, h = bh & 15, g = h >> 2;
    uint32_t smb = (uint32_t)__cvta_generic_to_shared(sm);

    // ---- stage Q (128 rows x 64) into stage-0 region, hoist fragments ----
    const float* qsrc = g_qkv + (size_t)(b * SEQ + qt * 128) * QKV_N + h * DHEAD;
#pragma unroll
    for (int i = 0; i < 8; i++) {
        int idx = tid + i * 256;
        int r = idx >> 4, c = (idx & 15) * 4;
        cpa16(smb + (uint32_t)(r * 68 + c) * 4, qsrc + (size_t)r * QKV_N + c);
    }
    CP_COMMIT(); cp_wait<0>();
    __syncthreads();

    uint32_t Qf[8][4];
    {
        int r0 = 16 * w + l4;
#pragma unroll
        for (int ks = 0; ks < 8; ks++) {
            Qf[ks][0] = fbits(sm[(r0    ) * 68 + 8 * ks + lm4]);
            Qf[ks][1] = fbits(sm[(r0 + 8) * 68 + 8 * ks + lm4]);
            Qf[ks][2] = fbits(sm[(r0    ) * 68 + 8 * ks + lm4 + 4]);
            Qf[ks][3] = fbits(sm[(r0 + 8) * 68 + 8 * ks + lm4 + 4]);
        }
    }
    __syncthreads();

    const float* kb0 = g_qkv + (size_t)(b * SEQ) * QKV_N + DIM + g * DHEAD;
    const float* vb0 = kb0 + KVD / 2;

#define KVFILL(kt, st)                                                         \
    {                                                                          \
        const float* kbp = kb0 + (size_t)(kt) * 64 * QKV_N;                    \
        const float* vbp = vb0 + (size_t)(kt) * 64 * QKV_N;                    \
        uint32_t base = smb + (uint32_t)(st) * AT_STAGE * 4;                   \
        _Pragma("unroll")                                                      \
        for (int i = 0; i < 4; i++) {                                          \
            int idx = tid + i * 256;                                           \
            int r = idx >> 4, c = (idx & 15) * 4;                              \
            cpa16(base + (uint32_t)(r * 68 + c) * 4,                           \
                  kbp + (size_t)r * QKV_N + c);                                \
            cpa16(base + (uint32_t)(64 * 68 + r * 68 + c) * 4,                 \
                  vbp + (size_t)r * QKV_N + c);                                \
        }                                                                      \
        CP_COMMIT();                                                           \
    }

    KVFILL(0, 0);

    float Of[8][4];
#pragma unroll
    for (int nt = 0; nt < 8; nt++)
#pragma unroll
        for (int i = 0; i < 4; i++) Of[nt][i] = 0.f;
    float m0 = -CUDART_INF_F, m1 = -CUDART_INF_F, l0 = 0.f, l1 = 0.f;

    int srcA = (l4 << 2) | (lm4 >> 1);
    int srcB = srcA + 2;
    bool odd = lm4 & 1;

    const int NT = SEQ / 64;
    for (int kt = 0; kt < NT; kt++) {
        int s = kt & 1;
        if (kt + 1 < NT) { KVFILL(kt + 1, s ^ 1); cp_wait<1>(); }
        else             { cp_wait<0>(); }
        __syncthreads();

        const float* Ks = sm + s * AT_STAGE;
        const float* Vs = Ks + 64 * 68;

        // ---- S = Q K^T (exponent domain: q pre-scaled by 0.125*log2e) ----
        float Sa[8][4];
#pragma unroll
        for (int nt = 0; nt < 8; nt++)
#pragma unroll
            for (int i = 0; i < 4; i++) Sa[nt][i] = 0.f;
#pragma unroll
        for (int ks = 0; ks < 8; ks++)
#pragma unroll
            for (int nt = 0; nt < 8; nt++) {
                uint32_t bf[2];
                int key = 8 * nt + l4;
                bf[0] = fbits(Ks[key * 68 + 8 * ks + lm4]);
                bf[1] = fbits(Ks[key * 68 + 8 * ks + lm4 + 4]);
                mma8(Sa[nt], Qf[ks], bf);
            }

        // ---- warp-local online softmax (rows l4, l4+8) ----
        float pm0 = -CUDART_INF_F, pm1 = -CUDART_INF_F;
#pragma unroll
        for (int nt = 0; nt < 8; nt++) {
            pm0 = fmaxf(pm0, fmaxf(Sa[nt][0], Sa[nt][1]));
            pm1 = fmaxf(pm1, fmaxf(Sa[nt][2], Sa[nt][3]));
        }
        pm0 = fmaxf(pm0, __shfl_xor_sync(0xffffffffu, pm0, 1));
        pm0 = fmaxf(pm0, __shfl_xor_sync(0xffffffffu, pm0, 2));
        pm1 = fmaxf(pm1, __shfl_xor_sync(0xffffffffu, pm1, 1));
        pm1 = fmaxf(pm1, __shfl_xor_sync(0xffffffffu, pm1, 2));
        float mn0 = fmaxf(m0, pm0), mn1 = fmaxf(m1, pm1);
        float al0 = exp2f(m0 - mn0), al1 = exp2f(m1 - mn1);
        m0 = mn0; m1 = mn1;
        float s0 = 0.f, s1 = 0.f;
#pragma unroll
        for (int nt = 0; nt < 8; nt++) {
            Sa[nt][0] = exp2f(Sa[nt][0] - mn0); s0 += Sa[nt][0];
            Sa[nt][1] = exp2f(Sa[nt][1] - mn0); s0 += Sa[nt][1];
            Sa[nt][2] = exp2f(Sa[nt][2] - mn1); s1 += Sa[nt][2];
            Sa[nt][3] = exp2f(Sa[nt][3] - mn1); s1 += Sa[nt][3];
        }
        s0 += __shfl_xor_sync(0xffffffffu, s0, 1);
        s0 += __shfl_xor_sync(0xffffffffu, s0, 2);
        s1 += __shfl_xor_sync(0xffffffffu, s1, 1);
        s1 += __shfl_xor_sync(0xffffffffu, s1, 2);
        l0 = l0 * al0 + s0;
        l1 = l1 * al1 + s1;
#pragma unroll
        for (int nt = 0; nt < 8; nt++) {
            Of[nt][0] *= al0; Of[nt][1] *= al0;
            Of[nt][2] *= al1; Of[nt][3] *= al1;
        }

        // ---- O += P V : shuffle C-frag -> A-frag per 8-key chunk ----
#pragma unroll
        for (int kc = 0; kc < 8; kc++) {
            float u0 = __shfl_sync(0xffffffffu, Sa[kc][0], srcA);
            float u1 = __shfl_sync(0xffffffffu, Sa[kc][1], srcA);
            float u2 = __shfl_sync(0xffffffffu, Sa[kc][2], srcA);
            float u3 = __shfl_sync(0xffffffffu, Sa[kc][3], srcA);
            float v0 = __shfl_sync(0xffffffffu, Sa[kc][0], srcB);
            float v1 = __shfl_sync(0xffffffffu, Sa[kc][1], srcB);
            float v2 = __shfl_sync(0xffffffffu, Sa[kc][2], srcB);
            float v3 = __shfl_sync(0xffffffffu, Sa[kc][3], srcB);
            uint32_t pa[4];
            pa[0] = fbits(tf32r(odd ? u1 : u0));
            pa[1] = fbits(tf32r(odd ? u3 : u2));
            pa[2] = fbits(tf32r(odd ? v1 : v0));
            pa[3] = fbits(tf32r(odd ? v3 : v2));
#pragma unroll
            for (int dnt = 0; dnt < 8; dnt++) {
                uint32_t bf[2];
                int d0 = 8 * dnt + l4;
                bf[0] = fbits(Vs[(8 * kc + lm4    ) * 68 + d0]);
                bf[1] = fbits(Vs[(8 * kc + lm4 + 4) * 68 + d0]);
                mma8(Of[dnt], pa, bf);
            }
        }
        __syncthreads();
    }
#undef KVFILL

    // ---- epilogue: 1/l scale, tf32 round (feeds cp.async GEMM), store ----
    float i0 = 1.f / l0, i1 = 1.f / l1;
    int r = b * SEQ + qt * 128 + 16 * w + l4;
#pragma unroll
    for (int dnt = 0; dnt < 8; dnt++) {
        int c = h * DHEAD + 8 * dnt + 2 * lm4;
        float* o0 = g_ao + (size_t)r * DIM + c;
        *(float2*)o0 = make_float2(tf32r(Of[dnt][0] * i0), tf32r(Of[dnt][1] * i0));
        float* o1 = o0 + (size_t)8 * DIM;
        *(float2*)o1 = make_float2(tf32r(Of[dnt][2] * i1), tf32r(Of[dnt][3] * i1));
    }
}

// ---------------------------------------------------------------------------
extern "C" void kernel_launch(void* const* d_in, const int* in_sizes, int n_in,
                              void* d_out, int out_size) {
    (void)in_sizes; (void)n_in; (void)out_size;
    const float* x    = (const float*)d_in[0];
    const float* ln_s = (const float*)d_in[1];
    const float* ln_b = (const float*)d_in[2];
    const float* Wq   = (const float*)d_in[3];
    const float* Wkv  = (const float*)d_in[4];
    const float* qn_s = (const float*)d_in[5];
    const float* qn_b = (const float*)d_in[6];
    const float* kn_s = (const float*)d_in[7];
    const float* kn_b = (const float*)d_in[8];
    const float* Wout = (const float*)d_in[9];
    float* out = (float*)d_out;

    cudaFuncSetAttribute(attn_kernel,
                         cudaFuncAttributeMaxDynamicSharedMemorySize, ATTN_SMEM);

    int wtot = (DIM * DIM + DIM * KVD + DIM * DIM) / 4;   // float4 units
    round_weights<<<(wtot + 255) / 256, 256>>>(Wq, Wkv, Wout);
    ln_rows<<<M_ROWS, 256>>>(x, ln_s, ln_b);
    gemm_qkv<<<dim3(12, M_ROWS / 128), 256>>>();
    head_ln<<<dim3(M_ROWS, 24), 32>>>(qn_s, qn_b, kn_s, kn_b);
    attn_kernel<<<dim3(SEQ / 128, BATCH * HEADS), 256, ATTN_SMEM>>>();
    gemm_out<<<dim3(DIM / 128, M_ROWS / 128), 256>>>(out);
}